// round 6
// baseline (speedup 1.0000x reference)
#include <cuda_runtime.h>
#include <math.h>

#define D 32
#define H 128
#define B 128
#define NSTEPS 8
#define NTHREADS 512
#define LOG2PI 1.8378770664093453f
#define DT 0.125f

// A[q][p] = W2[p][q] * M[q][p],  M = W1 @ W3  (trace(J) = d2^T (A d1))
__device__ float g_A[H * H];

__global__ void prep_A_kernel(const float* __restrict__ W1,
                              const float* __restrict__ W2,
                              const float* __restrict__ W3) {
    int q = blockIdx.x;
    int p = threadIdx.x;
    float m = 0.f;
#pragma unroll
    for (int i = 0; i < D; ++i)
        m = fmaf(W1[q * D + i], W3[i * H + p], m);
    g_A[q * H + p] = W2[p * H + q] * m;
}

__constant__ float c_c[6] = {0.f, 0.2f, 0.3f, 0.8f, 8.f / 9.f, 1.f};
__constant__ float c_a[6][5] = {
    {0.f, 0.f, 0.f, 0.f, 0.f},
    {0.2f, 0.f, 0.f, 0.f, 0.f},
    {3.f / 40.f, 9.f / 40.f, 0.f, 0.f, 0.f},
    {44.f / 45.f, -56.f / 15.f, 32.f / 9.f, 0.f, 0.f},
    {19372.f / 6561.f, -25360.f / 2187.f, 64448.f / 6561.f, -212.f / 729.f, 0.f},
    {9017.f / 3168.f, -355.f / 33.f, 46732.f / 5247.f, 49.f / 176.f, -5103.f / 18656.f}};
__constant__ float c_b[6] = {35.f / 384.f, 0.f, 500.f / 1113.f, 125.f / 192.f,
                             -2187.f / 6784.f, 11.f / 84.f};

__device__ __forceinline__ float tanh_fast(float x) {
    float r;
    asm("tanh.approx.f32 %0, %1;" : "=f"(r) : "f"(x));
    return r;
}

// shared memory layout (floats) — all 16B-aligned where vector-accessed
#define OFF_HD2  0                    // float2 x 128 = 256 floats
#define OFF_H2S  256                  // 128
#define OFF_PART 384                  // 512
#define OFF_XS   896                  // 32
#define OFF_REDW 928                  // 16
#define SMEM_FLOATS 944
#define SMEM_BYTES (SMEM_FLOATS * sizeof(float))

__global__ __launch_bounds__(NTHREADS, 1) void ode_kernel(
    const float* __restrict__ x0g, const float* __restrict__ W1g,
    const float* __restrict__ u1g, const float* __restrict__ b1g,
    const float* __restrict__ W2g, const float* __restrict__ b2g,
    const float* __restrict__ W3g, const float* __restrict__ b3g,
    const float* __restrict__ precg, float* __restrict__ out) {
    extern __shared__ float sm[];
    float2* hd2 = (float2*)(sm + OFF_HD2);
    float* h2s = sm + OFF_H2S;
    float* part = sm + OFF_PART;
    float* xs = sm + OFF_XS;
    float* redw = sm + OFF_REDW;

    const int tid = threadIdx.x;
    const int b = blockIdx.x;
    const int w = tid >> 5, lane = tid & 31;
    const int pp = lane >> 2, cc = lane & 3;   // warp-local: output pp, chunk cc
    const int p = w * 8 + pp;                  // output index in H (PA/PB)
    const int i3 = tid & 31, g3 = tid >> 5;    // PC mapping

    // ---- register-cached weights (loaded once) ----
    float W2r[32], Ar[32], W1r[8], W3r[8];
#pragma unroll
    for (int j = 0; j < 32; ++j) {
        int q = cc * 32 + j;
        W2r[j] = W2g[p * H + q];
        Ar[j] = g_A[q * H + p];
    }
#pragma unroll
    for (int j = 0; j < 8; ++j)
        W1r[j] = W1g[p * D + cc * 8 + j];
#pragma unroll
    for (int j = 0; j < 8; ++j)
        W3r[j] = W3g[i3 * H + g3 * 8 + j];
    const float u1r = u1g[p], b1r = b1g[p], b2r = b2g[p];

    // warp-0 state (per-lane i = lane)
    float b3r = 0.f, precr = 0.f, xcur_r = 0.f, xs_r = 0.f;
    float xacc = 0.f, lacc = 0.f, kacc = 0.f;
    float ksr[6];
    if (tid < 32) {
        b3r = b3g[lane];
        precr = precg[lane];
        xcur_r = x0g[b * D + lane];
        xs_r = xcur_r;
        xs[lane] = xcur_r;
    }
    __syncthreads();

#pragma unroll 1
    for (int s = 0; s < NSTEPS; ++s) {
        const float t0 = (float)s * DT;
#pragma unroll
        for (int st = 0; st < 6; ++st) {
            const float t = fmaf(c_c[st], DT, t0);

            // ---- PA: z1 partial (8 FMA) + in-warp reduce + h1 ----
            {
                const float4* xs4 = (const float4*)xs;
                float4 xa = xs4[cc * 2];
                float4 xb = xs4[cc * 2 + 1];
                float acc = W1r[0] * xa.x;
                acc = fmaf(W1r[1], xa.y, acc);
                acc = fmaf(W1r[2], xa.z, acc);
                acc = fmaf(W1r[3], xa.w, acc);
                acc = fmaf(W1r[4], xb.x, acc);
                acc = fmaf(W1r[5], xb.y, acc);
                acc = fmaf(W1r[6], xb.z, acc);
                acc = fmaf(W1r[7], xb.w, acc);
                acc += __shfl_xor_sync(0xffffffffu, acc, 1);
                acc += __shfl_xor_sync(0xffffffffu, acc, 2);
                float z1 = fmaf(t, u1r, acc + b1r);
                float h1 = tanh_fast(z1);
                if (cc == 0) hd2[p] = make_float2(h1, 1.f - h1 * h1);
            }
            __syncthreads();

            // ---- PB: z2/av over q-chunk + in-warp reduce + h2 + trace partial ----
            {
                const float4* hd4 = ((const float4*)hd2) + cc * 16;
                float z2a = 0.f, z2b = 0.f, ava = 0.f, avb = 0.f;
#pragma unroll
                for (int j = 0; j < 16; ++j) {
                    float4 hh = hd4[j];  // {h1[2j], d1[2j], h1[2j+1], d1[2j+1]}
                    z2a = fmaf(W2r[2 * j], hh.x, z2a);
                    ava = fmaf(Ar[2 * j], hh.y, ava);
                    z2b = fmaf(W2r[2 * j + 1], hh.z, z2b);
                    avb = fmaf(Ar[2 * j + 1], hh.w, avb);
                }
                float z2 = z2a + z2b, av = ava + avb;
                z2 += __shfl_xor_sync(0xffffffffu, z2, 1);
                z2 += __shfl_xor_sync(0xffffffffu, z2, 2);
                av += __shfl_xor_sync(0xffffffffu, av, 1);
                av += __shfl_xor_sync(0xffffffffu, av, 2);
                float h2 = tanh_fast(z2 + b2r);
                if (cc == 0) h2s[p] = h2;
                float trv = (1.f - h2 * h2) * av;   // replicated x4 over cc
                trv += __shfl_xor_sync(0xffffffffu, trv, 4);
                trv += __shfl_xor_sync(0xffffffffu, trv, 8);
                trv += __shfl_xor_sync(0xffffffffu, trv, 16);
                if (lane == 0) redw[w] = trv;       // sum over this warp's 8 p's
            }
            __syncthreads();

            // ---- PC: W3 partials ----
            {
                const float4* h24 = ((const float4*)h2s) + g3 * 2;
                float4 ha = h24[0];
                float4 hb = h24[1];
                float o = W3r[0] * ha.x;
                o = fmaf(W3r[1], ha.y, o);
                o = fmaf(W3r[2], ha.z, o);
                o = fmaf(W3r[3], ha.w, o);
                o = fmaf(W3r[4], hb.x, o);
                o = fmaf(W3r[5], hb.y, o);
                o = fmaf(W3r[6], hb.z, o);
                o = fmaf(W3r[7], hb.w, o);
                part[g3 * 32 + i3] = o;
            }
            __syncthreads();

            // ---- PD: finalize k_st + scalars + next stage x (warp 0) ----
            if (tid < 32) {
                float dx = b3r;
#pragma unroll
                for (int g = 0; g < 16; ++g)
                    dx += part[g * 32 + lane];
                ksr[st] = dx;
                float lp = fmaf(-0.5f * xs_r, xs_r, -0.5f * LOG2PI);
                float s1 = lp * dx;
                float s2 = -precr * xs_r * dx;
                float trp = (lane < 16) ? redw[lane] : 0.f;
#pragma unroll
                for (int off = 16; off; off >>= 1) {
                    s1 += __shfl_xor_sync(0xffffffffu, s1, off);
                    s2 += __shfl_xor_sync(0xffffffffu, s2, off);
                    trp += __shfl_xor_sync(0xffffffffu, trp, off);
                }
                xacc = fmaf(DT * c_b[st], dx, xacc);
                if (lane == 0) {
                    float dlogp = -trp;
                    float omt = 1.f - t;
                    float dkl = fmaf(-0.5f * omt * omt, s1,
                                fmaf(-0.5f * omt * (1.f + t), s2, omt * dlogp));
                    lacc = fmaf(DT * c_b[st], dlogp, lacc);
                    kacc = fmaf(DT * c_b[st], dkl, kacc);
                }
                if (st < 5) {
                    float xv = xcur_r;
#pragma unroll
                    for (int j = 0; j <= st; ++j)
                        xv = fmaf(DT * c_a[st + 1][j], ksr[j], xv);
                    xs_r = xv;
                } else {
                    xcur_r += xacc;
                    xacc = 0.f;
                    xs_r = xcur_r;
                }
                xs[lane] = xs_r;
            }
            __syncthreads();
        }
    }

    // ---- outputs: z [B*D], logp [B], kl [B] ----
    if (tid < 32) {
        out[b * D + lane] = xcur_r;
        float x0v = x0g[b * D + lane];
        float lp = fmaf(-0.5f * x0v, x0v, -0.5f * LOG2PI);
#pragma unroll
        for (int off = 16; off; off >>= 1)
            lp += __shfl_xor_sync(0xffffffffu, lp, off);
        if (lane == 0) {
            out[B * D + b] = lp + lacc;
            out[B * D + B + b] = kacc;
        }
    }
}

extern "C" void kernel_launch(void* const* d_in, const int* in_sizes, int n_in,
                              void* d_out, int out_size) {
    const float* x0 = (const float*)d_in[0];
    const float* W1 = (const float*)d_in[1];
    const float* u1 = (const float*)d_in[2];
    const float* b1 = (const float*)d_in[3];
    const float* W2 = (const float*)d_in[4];
    const float* b2 = (const float*)d_in[5];
    const float* W3 = (const float*)d_in[6];
    const float* b3 = (const float*)d_in[7];
    const float* prec = (const float*)d_in[8];
    float* out = (float*)d_out;

    prep_A_kernel<<<H, H>>>(W1, W2, W3);
    ode_kernel<<<B, NTHREADS, SMEM_BYTES>>>(x0, W1, u1, b1, W2, b2, W3, b3, prec, out);
}

// round 7
// speedup vs baseline: 1.0433x; 1.0433x over previous
#include <cuda_runtime.h>
#include <math.h>

#define D 32
#define H 128
#define B 128
#define NSTEPS 8
#define NTHREADS 512
#define LOG2PI 1.8378770664093453f
#define DT 0.125f

// A[q][p] = W2[p][q] * M[q][p],  M = W1 @ W3  (trace(J) = d2^T (A d1))
__device__ float g_A[H * H];

__global__ void prep_A_kernel(const float* __restrict__ W1,
                              const float* __restrict__ W2,
                              const float* __restrict__ W3) {
    int q = blockIdx.x;
    int p = threadIdx.x;
    float m = 0.f;
#pragma unroll
    for (int i = 0; i < D; ++i)
        m = fmaf(W1[q * D + i], W3[i * H + p], m);
    g_A[q * H + p] = W2[p * H + q] * m;
}

__constant__ float c_c[6] = {0.f, 0.2f, 0.3f, 0.8f, 8.f / 9.f, 1.f};
__constant__ float c_a[6][5] = {
    {0.f, 0.f, 0.f, 0.f, 0.f},
    {0.2f, 0.f, 0.f, 0.f, 0.f},
    {3.f / 40.f, 9.f / 40.f, 0.f, 0.f, 0.f},
    {44.f / 45.f, -56.f / 15.f, 32.f / 9.f, 0.f, 0.f},
    {19372.f / 6561.f, -25360.f / 2187.f, 64448.f / 6561.f, -212.f / 729.f, 0.f},
    {9017.f / 3168.f, -355.f / 33.f, 46732.f / 5247.f, 49.f / 176.f, -5103.f / 18656.f}};
__constant__ float c_b[6] = {35.f / 384.f, 0.f, 500.f / 1113.f, 125.f / 192.f,
                             -2187.f / 6784.f, 11.f / 84.f};

__device__ __forceinline__ float tanh_fast(float x) {
    float r;
    asm("tanh.approx.f32 %0, %1;" : "=f"(r) : "f"(x));
    return r;
}

// shared memory layout (floats), 16B alignment where vector-accessed
#define OFF_HD2  0                    // float2 x 128 = 256
#define OFF_H2S  256                  // 128
#define OFF_PART 384                  // 512
#define OFF_XS   896                  // 32
#define OFF_REDW 928                  // 16
#define OFF_KS   944                  // 6*34 = 204
#define SMEM_FLOATS (OFF_KS + 204)
#define SMEM_BYTES (SMEM_FLOATS * sizeof(float))

__global__ __launch_bounds__(NTHREADS, 1) void ode_kernel(
    const float* __restrict__ x0g, const float* __restrict__ W1g,
    const float* __restrict__ u1g, const float* __restrict__ b1g,
    const float* __restrict__ W2g, const float* __restrict__ b2g,
    const float* __restrict__ W3g, const float* __restrict__ b3g,
    const float* __restrict__ precg, float* __restrict__ out) {
    extern __shared__ float sm[];
    float2* hd2 = (float2*)(sm + OFF_HD2);
    float* h2s = sm + OFF_H2S;
    float* part = sm + OFF_PART;
    float* xs = sm + OFF_XS;
    float* redw = sm + OFF_REDW;
    float* ks = sm + OFF_KS;

    const int tid = threadIdx.x;
    const int b = blockIdx.x;
    const int w = tid >> 5, lane = tid & 31;
    const int pp = lane >> 2, cc = lane & 3;   // warp-local: output pp, chunk cc
    const int p = w * 8 + pp;                  // output index in H (PA/PB)
    const int i3 = tid & 31, g3 = tid >> 5;    // PC mapping

    // ---- register-cached weights (loaded once) ----
    float W2r[32], Ar[32], W1r[8], W3r[8];
#pragma unroll
    for (int j = 0; j < 32; ++j) {
        int q = cc * 32 + j;
        W2r[j] = W2g[p * H + q];
        Ar[j] = g_A[q * H + p];
    }
#pragma unroll
    for (int j = 0; j < 8; ++j)
        W1r[j] = W1g[p * D + cc * 8 + j];
#pragma unroll
    for (int j = 0; j < 8; ++j)
        W3r[j] = W3g[i3 * H + g3 * 8 + j];
    const float u1r = u1g[p], b1r = b1g[p], b2r = b2g[p];

    // warp-0 per-lane state
    float b3r = 0.f, precr = 0.f, xcur_r = 0.f, xs_r = 0.f;
    float xacc = 0.f, lacc = 0.f, kacc = 0.f;
    if (tid < 32) {
        b3r = b3g[lane];
        precr = precg[lane];
        xcur_r = x0g[b * D + lane];
        xs_r = xcur_r;
        xs[lane] = xcur_r;
    }
    __syncthreads();

#pragma unroll 1
    for (int s = 0; s < NSTEPS; ++s) {
        const float t0 = (float)s * DT;
#pragma unroll 1
        for (int st = 0; st < 6; ++st) {
            const float t = fmaf(c_c[st], DT, t0);

            // ---- PA: z1 partial (8 FMA) + in-warp reduce + h1 ----
            {
                const float4* xs4 = (const float4*)xs;
                float4 xa = xs4[cc * 2];
                float4 xb = xs4[cc * 2 + 1];
                float acc = W1r[0] * xa.x;
                acc = fmaf(W1r[1], xa.y, acc);
                acc = fmaf(W1r[2], xa.z, acc);
                acc = fmaf(W1r[3], xa.w, acc);
                acc = fmaf(W1r[4], xb.x, acc);
                acc = fmaf(W1r[5], xb.y, acc);
                acc = fmaf(W1r[6], xb.z, acc);
                acc = fmaf(W1r[7], xb.w, acc);
                acc += __shfl_xor_sync(0xffffffffu, acc, 1);
                acc += __shfl_xor_sync(0xffffffffu, acc, 2);
                float z1 = fmaf(t, u1r, acc + b1r);
                float h1 = tanh_fast(z1);
                if (cc == 0) hd2[p] = make_float2(h1, 1.f - h1 * h1);
            }
            __syncthreads();

            // ---- PB: z2/av over q-chunk + in-warp reduce + h2 + trace partial ----
            {
                const float4* hd4 = ((const float4*)hd2) + cc * 16;
                float z2a = 0.f, z2b = 0.f, ava = 0.f, avb = 0.f;
#pragma unroll
                for (int j = 0; j < 16; ++j) {
                    float4 hh = hd4[j];  // {h1[2j], d1[2j], h1[2j+1], d1[2j+1]}
                    z2a = fmaf(W2r[2 * j], hh.x, z2a);
                    ava = fmaf(Ar[2 * j], hh.y, ava);
                    z2b = fmaf(W2r[2 * j + 1], hh.z, z2b);
                    avb = fmaf(Ar[2 * j + 1], hh.w, avb);
                }
                float z2 = z2a + z2b, av = ava + avb;
                z2 += __shfl_xor_sync(0xffffffffu, z2, 1);
                z2 += __shfl_xor_sync(0xffffffffu, z2, 2);
                av += __shfl_xor_sync(0xffffffffu, av, 1);
                av += __shfl_xor_sync(0xffffffffu, av, 2);
                float h2 = tanh_fast(z2 + b2r);
                if (cc == 0) h2s[p] = h2;
                float trv = (1.f - h2 * h2) * av;   // identical across cc lanes
                trv += __shfl_xor_sync(0xffffffffu, trv, 4);
                trv += __shfl_xor_sync(0xffffffffu, trv, 8);
                trv += __shfl_xor_sync(0xffffffffu, trv, 16);
                if (lane == 0) redw[w] = trv;       // sum over this warp's 8 p's
            }
            __syncthreads();

            // ---- PC: W3 partials ----
            {
                const float4* h24 = ((const float4*)h2s) + g3 * 2;
                float4 ha = h24[0];
                float4 hb = h24[1];
                float o = W3r[0] * ha.x;
                o = fmaf(W3r[1], ha.y, o);
                o = fmaf(W3r[2], ha.z, o);
                o = fmaf(W3r[3], ha.w, o);
                o = fmaf(W3r[4], hb.x, o);
                o = fmaf(W3r[5], hb.y, o);
                o = fmaf(W3r[6], hb.z, o);
                o = fmaf(W3r[7], hb.w, o);
                part[g3 * 32 + i3] = o;
            }
            __syncthreads();

            // ---- PD: finalize k_st + scalars + next stage x (warp 0) ----
            if (tid < 32) {
                float dx = b3r;
#pragma unroll
                for (int g = 0; g < 16; ++g)
                    dx += part[g * 32 + lane];
                ks[st * 34 + lane] = dx;
                float lp = fmaf(-0.5f * xs_r, xs_r, -0.5f * LOG2PI);
                float omt = 1.f - t;
                // fused KL contribution: -0.5*omt^2*lp*dx - 0.5*omt*(1+t)*(-prec*x)*dx
                float contrib = fmaf(-0.5f * omt * omt, lp,
                                     0.5f * omt * (1.f + t) * precr * xs_r) * dx;
                float trp = (lane < 16) ? redw[lane] : 0.f;
#pragma unroll
                for (int off = 16; off; off >>= 1) {
                    contrib += __shfl_xor_sync(0xffffffffu, contrib, off);
                    trp += __shfl_xor_sync(0xffffffffu, trp, off);
                }
                float bst = DT * c_b[st];
                xacc = fmaf(bst, dx, xacc);
                if (lane == 0) {
                    float dlogp = -trp;
                    lacc = fmaf(bst, dlogp, lacc);
                    kacc = fmaf(bst, contrib + omt * dlogp, kacc);
                }
                if (st < 5) {
                    float xn = xcur_r;
                    for (int j = 0; j <= st; ++j)
                        xn = fmaf(DT * c_a[st + 1][j], ks[j * 34 + lane], xn);
                    xs_r = xn;
                } else {
                    xcur_r += xacc;
                    xacc = 0.f;
                    xs_r = xcur_r;
                }
                xs[lane] = xs_r;
            }
            __syncthreads();
        }
    }

    // ---- outputs: z [B*D], logp [B], kl [B] ----
    if (tid < 32) {
        out[b * D + lane] = xcur_r;
        float x0v = x0g[b * D + lane];
        float lp = fmaf(-0.5f * x0v, x0v, -0.5f * LOG2PI);
#pragma unroll
        for (int off = 16; off; off >>= 1)
            lp += __shfl_xor_sync(0xffffffffu, lp, off);
        if (lane == 0) {
            out[B * D + b] = lp + lacc;
            out[B * D + B + b] = kacc;
        }
    }
}

extern "C" void kernel_launch(void* const* d_in, const int* in_sizes, int n_in,
                              void* d_out, int out_size) {
    const float* x0 = (const float*)d_in[0];
    const float* W1 = (const float*)d_in[1];
    const float* u1 = (const float*)d_in[2];
    const float* b1 = (const float*)d_in[3];
    const float* W2 = (const float*)d_in[4];
    const float* b2 = (const float*)d_in[5];
    const float* W3 = (const float*)d_in[6];
    const float* b3 = (const float*)d_in[7];
    const float* prec = (const float*)d_in[8];
    float* out = (float*)d_out;

    prep_A_kernel<<<H, H>>>(W1, W2, W3);
    ode_kernel<<<B, NTHREADS, SMEM_BYTES>>>(x0, W1, u1, b1, W2, b2, W3, b3, prec, out);
}